// round 1
// baseline (speedup 1.0000x reference)
#include <cuda_runtime.h>
#include <cstdint>
#include <cstddef>

// Problem constants
#define M_TOT  8192   // B * SEQ
#define DIN    4096
#define DOUT   4096
#define RANK   1024

// Tiling
#define BM 128
#define BN 128
#define BK 32
#define PAD 4
#define LDS_ROW (BK + PAD)     // 36 floats per smem row
#define THREADS 256

// 32 MB scratch for T = (x @ Vh^T) * S   (allocation-free: __device__ global)
__device__ float g_T[(size_t)M_TOT * RANK];

__device__ __forceinline__ uint32_t f2tf32(float f) {
    uint32_t u;
    asm("cvt.rna.tf32.f32 %0, %1;" : "=r"(u) : "f"(f));
    return u;
}

__device__ __forceinline__ void cp_async16(uint32_t saddr, const void* gptr) {
    asm volatile("cp.async.cg.shared.global [%0], [%1], 16;\n" :: "r"(saddr), "l"(gptr));
}

// D[M,N] = A[M,K] * B[N,K]^T   (both row-major, K contiguous — NT GEMM)
// If SCALE: D[m,n] *= S[n] in the epilogue.
template <bool SCALE>
__global__ __launch_bounds__(THREADS, 2)
void gemm_tf32_nt(const float* __restrict__ A, const float* __restrict__ Bm,
                  const float* __restrict__ S, float* __restrict__ D,
                  int M, int N, int K)
{
    extern __shared__ float smem[];
    float* As = smem;                          // [2][BM][LDS_ROW]
    float* Bs = smem + 2 * BM * LDS_ROW;       // [2][BN][LDS_ROW]

    const int tid  = threadIdx.x;
    const int warp = tid >> 5;
    const int lane = tid & 31;
    const int wm = warp & 3;        // 4 warps along M, each 32 rows
    const int wn = warp >> 2;       // 2 warps along N, each 64 cols
    const int gm = lane >> 2;       // groupID
    const int tg = lane & 3;        // threadID_in_group

    const int bm = blockIdx.y * BM;
    const int bn = blockIdx.x * BN;

    const float* Agb = A  + (size_t)bm * K;
    const float* Bgb = Bm + (size_t)bn * K;

    float acc[2][8][4];
    #pragma unroll
    for (int i = 0; i < 2; i++)
        #pragma unroll
        for (int j = 0; j < 8; j++)
            #pragma unroll
            for (int k = 0; k < 4; k++) acc[i][j][k] = 0.f;

    // Tile loader: BM(BN) x BK floats = 1024 float4 per matrix; 4 per thread.
    auto load_tile = [&](int kt, int buf) {
        float* Asb = As + buf * BM * LDS_ROW;
        float* Bsb = Bs + buf * BN * LDS_ROW;
        const float* Ag = Agb + (size_t)kt * BK;
        const float* Bg = Bgb + (size_t)kt * BK;
        #pragma unroll
        for (int i = 0; i < 4; i++) {
            int idx = tid + i * THREADS;
            int r   = idx >> 3;
            int c   = (idx & 7) * 4;
            cp_async16((uint32_t)__cvta_generic_to_shared(Asb + r * LDS_ROW + c),
                       Ag + (size_t)r * K + c);
            cp_async16((uint32_t)__cvta_generic_to_shared(Bsb + r * LDS_ROW + c),
                       Bg + (size_t)r * K + c);
        }
        asm volatile("cp.async.commit_group;\n");
    };

    const int nk = K / BK;
    load_tile(0, 0);

    for (int kt = 0; kt < nk; kt++) {
        if (kt + 1 < nk) {
            load_tile(kt + 1, (kt + 1) & 1);
            asm volatile("cp.async.wait_group 1;\n");
        } else {
            asm volatile("cp.async.wait_group 0;\n");
        }
        __syncthreads();

        const float* Asb = As + (kt & 1) * BM * LDS_ROW + (wm * 32) * LDS_ROW;
        const float* Bsb = Bs + (kt & 1) * BN * LDS_ROW + (wn * 64) * LDS_ROW;

        #pragma unroll
        for (int ks = 0; ks < BK / 8; ks++) {
            const int kc = ks * 8 + tg;
            uint32_t a[2][4], b[8][2];
            #pragma unroll
            for (int mt = 0; mt < 2; mt++) {
                const float* ap = Asb + (mt * 16 + gm) * LDS_ROW + kc;
                a[mt][0] = f2tf32(ap[0]);
                a[mt][1] = f2tf32(ap[8 * LDS_ROW]);
                a[mt][2] = f2tf32(ap[4]);
                a[mt][3] = f2tf32(ap[8 * LDS_ROW + 4]);
            }
            #pragma unroll
            for (int nt = 0; nt < 8; nt++) {
                const float* bp = Bsb + (nt * 8 + gm) * LDS_ROW + kc;
                b[nt][0] = f2tf32(bp[0]);
                b[nt][1] = f2tf32(bp[4]);
            }
            #pragma unroll
            for (int mt = 0; mt < 2; mt++)
                #pragma unroll
                for (int nt = 0; nt < 8; nt++)
                    asm volatile(
                        "mma.sync.aligned.m16n8k8.row.col.f32.tf32.tf32.f32 "
                        "{%0,%1,%2,%3}, {%4,%5,%6,%7}, {%8,%9}, {%0,%1,%2,%3};\n"
                        : "+f"(acc[mt][nt][0]), "+f"(acc[mt][nt][1]),
                          "+f"(acc[mt][nt][2]), "+f"(acc[mt][nt][3])
                        : "r"(a[mt][0]), "r"(a[mt][1]), "r"(a[mt][2]), "r"(a[mt][3]),
                          "r"(b[nt][0]), "r"(b[nt][1]));
        }
        __syncthreads();
    }

    // Epilogue
    const int row0 = bm + wm * 32 + gm;
    const int col0 = bn + wn * 64 + tg * 2;
    #pragma unroll
    for (int mt = 0; mt < 2; mt++) {
        #pragma unroll
        for (int nt = 0; nt < 8; nt++) {
            const int r = row0 + mt * 16;
            const int c = col0 + nt * 8;
            float s0 = 1.f, s1 = 1.f;
            if (SCALE) { s0 = __ldg(S + c); s1 = __ldg(S + c + 1); }
            float2 v0 = make_float2(acc[mt][nt][0] * s0, acc[mt][nt][1] * s1);
            float2 v1 = make_float2(acc[mt][nt][2] * s0, acc[mt][nt][3] * s1);
            *reinterpret_cast<float2*>(D + (size_t)r * N + c)       = v0;
            *reinterpret_cast<float2*>(D + (size_t)(r + 8) * N + c) = v1;
        }
    }
}

extern "C" void kernel_launch(void* const* d_in, const int* in_sizes, int n_in,
                              void* d_out, int out_size)
{
    const float* x  = (const float*)d_in[0];   // [8192, 4096]
    const float* U  = (const float*)d_in[1];   // [4096, 1024]
    const float* S  = (const float*)d_in[2];   // [1024]
    const float* Vh = (const float*)d_in[3];   // [1024, 4096]
    float* y = (float*)d_out;                  // [8192, 4096]

    float* T = nullptr;
    cudaGetSymbolAddress((void**)&T, g_T);

    const int smem_bytes = 2 * (BM + BN) * LDS_ROW * (int)sizeof(float); // 73728
    cudaFuncSetAttribute(gemm_tf32_nt<true>,
                         cudaFuncAttributeMaxDynamicSharedMemorySize, smem_bytes);
    cudaFuncSetAttribute(gemm_tf32_nt<false>,
                         cudaFuncAttributeMaxDynamicSharedMemorySize, smem_bytes);

    dim3 blk(THREADS);
    // GEMM 1: T[8192,1024] = x @ Vh^T, scaled by S per column
    gemm_tf32_nt<true><<<dim3(RANK / BN, M_TOT / BM), blk, smem_bytes>>>(
        x, Vh, S, T, M_TOT, RANK, DIN);
    // GEMM 2: y[8192,4096] = T @ U^T
    gemm_tf32_nt<false><<<dim3(DOUT / BN, M_TOT / BM), blk, smem_bytes>>>(
        T, U, nullptr, y, M_TOT, DOUT, RANK);
}

// round 3
// speedup vs baseline: 3.0830x; 3.0830x over previous
#include <cuda_runtime.h>
#include <cstdint>
#include <cstddef>

// ---------------- problem constants ----------------
#define M_TOT 8192
#define DIN   4096
#define DOUT  4096
#define RANK  1024

// ---------------- shared tiling ----------------
#define BM 128
#define BN 256
#define BK 32
#define THREADS 512

// tcgen05 path smem layout
#define NSTAGE 4
#define A_STAGE_BYTES (BM * BK * 4)    // 16384
#define B_STAGE_BYTES (BN * BK * 4)    // 32768
#define SMEM_A_OFF 1024
#define SMEM_B_OFF (SMEM_A_OFF + NSTAGE * A_STAGE_BYTES)      // 66560
#define SMEM_TOTAL (SMEM_B_OFF + NSTAGE * B_STAGE_BYTES)      // 197632

// legacy path smem layout (3-stage, padded rows, fits inside SMEM_TOTAL)
#define L_ROW 36                        // floats per smem row (36 mod 32 == 4: conflict-free)
#define LA_STAGE (BM * L_ROW * 4)       // 18432
#define LB_STAGE (BN * L_ROW * 4)       // 36864
#define L_A_OFF 1024
#define L_B_OFF (L_A_OFF + 3 * LA_STAGE)

// barrier offsets (first 1KB of smem)
#define OFF_TMEM  0
#define OFF_FULL  16
#define OFF_EMPTY 48
#define OFF_DONE  80

// tcgen05 idesc: kind::tf32, D=f32(1), A=tf32(2), B=tf32(2), N=128, M=128
#define IDESC_TF32 ((1u << 4) | (2u << 7) | (2u << 10) | ((128u / 8u) << 17) | ((128u / 16u) << 24))

// SW128 K-major smem descriptor base (layout=2, version=1, SBO=64, LBO=1)
#define DESC_BASE_SW128 \
    ((uint64_t(2) << 61) | (uint64_t(1) << 46) | (uint64_t(64) << 32) | (uint64_t(1) << 16))

// Feature gate: tcgen05 only exists on the accelerated target.
#if defined(__CUDA_ARCH__) && (defined(__CUDA_ARCH_FEAT_SM103_ALL) || defined(__CUDA_ARCH_FEAT_SM100_ALL) || defined(__CUDA_ARCH_FEAT_SM101_ALL))
#define TC_PATH 1
#else
#define TC_PATH 0
#endif

// ---------------- scratch (allocation-free) ----------------
__device__ __align__(16) float g_X [(size_t)M_TOT * DIN];   // rna(x)
__device__ __align__(16) float g_W1[(size_t)RANK  * DIN];   // rna(S[r] * Vh[r,k])
__device__ __align__(16) float g_W2[(size_t)DOUT  * RANK];  // rna(U)
__device__ __align__(16) float g_T [(size_t)M_TOT * RANK];  // intermediate (tf32-rounded)

// ---------------- helpers ----------------
__device__ __forceinline__ uint32_t f2tf32(float f) {
    uint32_t u;
    asm("cvt.rna.tf32.f32 %0, %1;" : "=r"(u) : "f"(f));
    return u;
}
__device__ __forceinline__ float rna_f(float f) { return __uint_as_float(f2tf32(f)); }

__device__ __forceinline__ uint32_t smem_u32(const void* p) {
    uint32_t a;
    asm("{ .reg .u64 t; cvta.to.shared.u64 t, %1; cvt.u32.u64 %0, t; }" : "=r"(a) : "l"(p));
    return a;
}
__device__ __forceinline__ void cp_async16(uint32_t saddr, const void* g) {
    asm volatile("cp.async.cg.shared.global [%0], [%1], 16;\n" :: "r"(saddr), "l"(g));
}
__device__ __forceinline__ uint32_t sw128(uint32_t o) { return o ^ ((o >> 3) & 0x70); }

#if TC_PATH
__device__ __forceinline__ void mbar_init(uint32_t a, uint32_t cnt) {
    asm volatile("mbarrier.init.shared.b64 [%0], %1;" :: "r"(a), "r"(cnt) : "memory");
}
__device__ __forceinline__ void mbar_arrive(uint32_t a) {
    asm volatile("mbarrier.arrive.shared.b64 _, [%0];" :: "r"(a) : "memory");
}
__device__ __forceinline__ void mbar_wait(uint32_t a, uint32_t parity) {
    asm volatile(
        "{\n\t"
        ".reg .pred P;\n\t"
        "W_%=:\n\t"
        "mbarrier.try_wait.parity.acquire.cta.shared::cta.b64 P, [%0], %1, 0x989680;\n\t"
        "@!P bra.uni W_%=;\n\t"
        "}" :: "r"(a), "r"(parity) : "memory");
}
__device__ __forceinline__ void mma_tf32_ss(uint32_t d_tmem, uint64_t a_desc, uint64_t b_desc,
                                            uint32_t idesc, uint32_t enable_d) {
    asm volatile(
        "{\n\t"
        ".reg .pred p;\n\t"
        "setp.ne.u32 p, %4, 0;\n\t"
        "tcgen05.mma.cta_group::1.kind::tf32 [%0], %1, %2, %3, {%5,%5,%5,%5}, p;\n\t"
        "}"
        :: "r"(d_tmem), "l"(a_desc), "l"(b_desc), "r"(idesc), "r"(enable_d), "r"(0u)
        : "memory");
}
__device__ __forceinline__ void tc_commit(uint32_t mbar) {
    asm volatile(
        "tcgen05.commit.cta_group::1.mbarrier::arrive::one.shared::cluster.b64 [%0];"
        :: "r"(mbar) : "memory");
}
__device__ __forceinline__ void ldtm_x32(uint32_t* r, uint32_t addr) {
    asm volatile(
        "tcgen05.ld.sync.aligned.32x32b.x32.b32 "
        "{%0, %1, %2, %3, %4, %5, %6, %7, "
        " %8, %9, %10, %11, %12, %13, %14, %15, "
        " %16, %17, %18, %19, %20, %21, %22, %23, "
        " %24, %25, %26, %27, %28, %29, %30, %31}, [%32];"
        : "=r"(r[0]),  "=r"(r[1]),  "=r"(r[2]),  "=r"(r[3]),
          "=r"(r[4]),  "=r"(r[5]),  "=r"(r[6]),  "=r"(r[7]),
          "=r"(r[8]),  "=r"(r[9]),  "=r"(r[10]), "=r"(r[11]),
          "=r"(r[12]), "=r"(r[13]), "=r"(r[14]), "=r"(r[15]),
          "=r"(r[16]), "=r"(r[17]), "=r"(r[18]), "=r"(r[19]),
          "=r"(r[20]), "=r"(r[21]), "=r"(r[22]), "=r"(r[23]),
          "=r"(r[24]), "=r"(r[25]), "=r"(r[26]), "=r"(r[27]),
          "=r"(r[28]), "=r"(r[29]), "=r"(r[30]), "=r"(r[31])
        : "r"(addr));
}
#endif  // TC_PATH

// ---------------- prepass kernels ----------------
__global__ void prep_round(const float* __restrict__ in, float* __restrict__ out, int n4) {
    int i = blockIdx.x * blockDim.x + threadIdx.x;
    int stride = gridDim.x * blockDim.x;
    for (; i < n4; i += stride) {
        float4 v = reinterpret_cast<const float4*>(in)[i];
        v.x = rna_f(v.x); v.y = rna_f(v.y); v.z = rna_f(v.z); v.w = rna_f(v.w);
        reinterpret_cast<float4*>(out)[i] = v;
    }
}
__global__ void prep_scale_round(const float* __restrict__ Vh, const float* __restrict__ S,
                                 float* __restrict__ out, int cols4) {
    int r = blockIdx.y;
    float s = __ldg(S + r);
    int c = blockIdx.x * blockDim.x + threadIdx.x;
    if (c < cols4) {
        float4 v = reinterpret_cast<const float4*>(Vh + (size_t)r * (cols4 * 4))[c];
        v.x = rna_f(v.x * s); v.y = rna_f(v.y * s); v.z = rna_f(v.z * s); v.w = rna_f(v.w * s);
        reinterpret_cast<float4*>(out + (size_t)r * (cols4 * 4))[c] = v;
    }
}

// ---------------- GEMM: D[M,Nout] = A[M,K] @ B[Nout,K]^T (all tf32-prerounded) ----------------
template <bool ROUND_OUT>
__global__ __launch_bounds__(THREADS, 1)
void gemm_nt(const float* __restrict__ A, const float* __restrict__ Bm,
             float* __restrict__ D, int K, int Nout)
{
    extern __shared__ char smem[];
    const uint32_t sbase = smem_u32(smem);
    const int tid  = threadIdx.x;
    const int warp = tid >> 5;
    const int lane = tid & 31;
    const int bm = blockIdx.y * BM;
    const int bn = blockIdx.x * BN;
    const int nk = K / BK;

#if TC_PATH
    // ================= tcgen05 warp-specialized path =================
    if (warp == 0) {
        asm volatile("tcgen05.alloc.cta_group::1.sync.aligned.shared::cta.b32 [%0], %1;"
                     :: "r"(sbase + OFF_TMEM), "r"(256u) : "memory");
        asm volatile("tcgen05.relinquish_alloc_permit.cta_group::1.sync.aligned;");
    }
    if (tid == 0) {
        #pragma unroll
        for (int s = 0; s < NSTAGE; s++) {
            mbar_init(sbase + OFF_FULL  + 8 * s, 256);  // 256 producer arrivals
            mbar_init(sbase + OFF_EMPTY + 8 * s, 1);    // 1 mma-commit arrival
        }
        mbar_init(sbase + OFF_DONE, 1);
    }
    __syncthreads();

    uint32_t tmem_base;
    asm volatile("ld.shared.b32 %0, [%1];" : "=r"(tmem_base) : "r"(sbase + OFF_TMEM));

    if (warp >= 8) {
        // ---- producers: 256 threads (warps 8-15) ----
        const int pt = tid - 256;
        int e_stage = 0, e_phase = 1;
        int pending = -1;
        const float* Agb = A  + (size_t)bm * K;
        const float* Bgb = Bm + (size_t)bn * K;
        for (int kt = 0; kt < nk; kt++) {
            const int s = e_stage;
            mbar_wait(sbase + OFF_EMPTY + 8 * s, (uint32_t)e_phase);
            if (++e_stage == NSTAGE) { e_stage = 0; e_phase ^= 1; }

            const float* Ag = Agb + (size_t)kt * BK;
            const uint32_t sA = sbase + SMEM_A_OFF + s * A_STAGE_BYTES;
            #pragma unroll
            for (int i = 0; i < 4; i++) {           // 1024 granules / 256 thr
                int idx = pt + 256 * i;
                int r = idx >> 3, g = idx & 7;
                cp_async16(sA + sw128((uint32_t)(r * 128 + g * 16)),
                           Ag + (size_t)r * K + g * 4);
            }
            const float* Bg = Bgb + (size_t)kt * BK;
            const uint32_t sB = sbase + SMEM_B_OFF + s * B_STAGE_BYTES;
            #pragma unroll
            for (int i = 0; i < 8; i++) {           // 2048 granules / 256 thr
                int idx = pt + 256 * i;
                int r = idx >> 3, g = idx & 7;
                cp_async16(sB + sw128((uint32_t)(r * 128 + g * 16)),
                           Bg + (size_t)r * K + g * 4);
            }
            asm volatile("cp.async.commit_group;\n");
            if (pending >= 0) {
                asm volatile("cp.async.wait_group 1;\n");
                asm volatile("fence.proxy.async.shared::cta;\n");
                mbar_arrive(sbase + OFF_FULL + 8 * pending);
            }
            pending = s;
        }
        asm volatile("cp.async.wait_group 0;\n");
        asm volatile("fence.proxy.async.shared::cta;\n");
        mbar_arrive(sbase + OFF_FULL + 8 * pending);
    } else if (warp == 0 && lane == 0) {
        // ---- MMA issuer: single thread ----
        int f_stage = 0, f_phase = 0;
        for (int kt = 0; kt < nk; kt++) {
            const int s = f_stage;
            mbar_wait(sbase + OFF_FULL + 8 * s, (uint32_t)f_phase);
            if (++f_stage == NSTAGE) { f_stage = 0; f_phase ^= 1; }

            uint64_t adesc = DESC_BASE_SW128 |
                (((uint64_t)((sbase + SMEM_A_OFF + s * A_STAGE_BYTES) >> 4)) & 0x3FFF);
            uint64_t bdesc = DESC_BASE_SW128 |
                (((uint64_t)((sbase + SMEM_B_OFF + s * B_STAGE_BYTES) >> 4)) & 0x3FFF);
            #pragma unroll
            for (int ks = 0; ks < 4; ks++) {        // K=8 per dispatch
                uint32_t en = (uint32_t)(kt | ks);
                mma_tf32_ss(tmem_base,       adesc + 2 * ks, bdesc + 2 * ks,        IDESC_TF32, en);
                mma_tf32_ss(tmem_base + 128, adesc + 2 * ks, bdesc + 1024 + 2 * ks, IDESC_TF32, en);
            }
            tc_commit(sbase + OFF_EMPTY + 8 * s);
        }
        tc_commit(sbase + OFF_DONE);
    }

    // ---- epilogue: warps 0-7 (each subpartition covered twice, split cols) ----
    mbar_wait(sbase + OFF_DONE, 0u);
    asm volatile("tcgen05.fence::after_thread_sync;" ::: "memory");

    if (warp < 8) {
        const size_t row = (size_t)(bm + (warp & 3) * 32 + lane);
        const int colh = (warp >> 2) * 128;
        float* drow = D + row * Nout + bn + colh;
        #pragma unroll
        for (int c = 0; c < 4; c++) {
            uint32_t r[32];
            ldtm_x32(r, tmem_base + colh + 32 * c);
            asm volatile("tcgen05.wait::ld.sync.aligned;" ::: "memory");
            if (ROUND_OUT) {
                #pragma unroll
                for (int j = 0; j < 32; j++) r[j] = f2tf32(__uint_as_float(r[j]));
            }
            float4* dst = reinterpret_cast<float4*>(drow + 32 * c);
            #pragma unroll
            for (int q = 0; q < 8; q++)
                dst[q] = make_float4(__uint_as_float(r[4 * q + 0]), __uint_as_float(r[4 * q + 1]),
                                     __uint_as_float(r[4 * q + 2]), __uint_as_float(r[4 * q + 3]));
        }
        asm volatile("tcgen05.fence::before_thread_sync;" ::: "memory");
    }
    __syncthreads();
    if (warp == 0) {
        asm volatile("tcgen05.dealloc.cta_group::1.sync.aligned.b32 %0, %1;"
                     :: "r"(tmem_base), "r"(256u));
    }

#else
    // ================= legacy mma.sync fallback (no a-features) =================
    const int gm = lane >> 2;       // 0..7
    const int tg = lane & 3;        // 0..3
    const int wm = warp & 1;        // 2 warps along M (64 rows each)
    const int wn = warp >> 1;       // 8 warps along N (32 cols each)

    float acc[4][4][4];
    #pragma unroll
    for (int i = 0; i < 4; i++)
        #pragma unroll
        for (int j = 0; j < 4; j++)
            #pragma unroll
            for (int k = 0; k < 4; k++) acc[i][j][k] = 0.f;

    const float* Agb = A  + (size_t)bm * K;
    const float* Bgb = Bm + (size_t)bn * K;

    auto load_tile = [&](int kt) {
        const int s = kt % 3;
        const float* Ag = Agb + (size_t)kt * BK;
        const uint32_t sA = sbase + L_A_OFF + s * LA_STAGE;
        #pragma unroll
        for (int j = 0; j < 2; j++) {               // 1024 granules / 512 thr
            int idx = tid + 512 * j;
            int r = idx >> 3, g = idx & 7;
            cp_async16(sA + (uint32_t)(r * L_ROW + g * 4) * 4,
                       Ag + (size_t)r * K + g * 4);
        }
        const float* Bg = Bgb + (size_t)kt * BK;
        const uint32_t sB = sbase + L_B_OFF + s * LB_STAGE;
        #pragma unroll
        for (int j = 0; j < 4; j++) {               // 2048 granules / 512 thr
            int idx = tid + 512 * j;
            int r = idx >> 3, g = idx & 7;
            cp_async16(sB + (uint32_t)(r * L_ROW + g * 4) * 4,
                       Bg + (size_t)r * K + g * 4);
        }
        asm volatile("cp.async.commit_group;\n");
    };

    load_tile(0);
    load_tile(1);

    for (int kt = 0; kt < nk; kt++) {
        if (kt + 1 < nk) asm volatile("cp.async.wait_group 1;\n");
        else             asm volatile("cp.async.wait_group 0;\n");
        __syncthreads();

        const int s = kt % 3;
        const uint32_t* Asb = reinterpret_cast<const uint32_t*>(smem + L_A_OFF + s * LA_STAGE)
                              + (wm * 64) * L_ROW;
        const uint32_t* Bsb = reinterpret_cast<const uint32_t*>(smem + L_B_OFF + s * LB_STAGE)
                              + (wn * 32) * L_ROW;

        #pragma unroll
        for (int ks = 0; ks < BK / 8; ks++) {
            const int kc = ks * 8 + tg;
            uint32_t a[4][4], b[4][2];
            #pragma unroll
            for (int mt = 0; mt < 4; mt++) {
                const uint32_t* ap = Asb + (mt * 16 + gm) * L_ROW + kc;
                a[mt][0] = ap[0];
                a[mt][1] = ap[8 * L_ROW];
                a[mt][2] = ap[4];
                a[mt][3] = ap[8 * L_ROW + 4];
            }
            #pragma unroll
            for (int nt = 0; nt < 4; nt++) {
                const uint32_t* bp = Bsb + (nt * 8 + gm) * L_ROW + kc;
                b[nt][0] = bp[0];
                b[nt][1] = bp[4];
            }
            #pragma unroll
            for (int mt = 0; mt < 4; mt++)
                #pragma unroll
                for (int nt = 0; nt < 4; nt++)
                    asm volatile(
                        "mma.sync.aligned.m16n8k8.row.col.f32.tf32.tf32.f32 "
                        "{%0,%1,%2,%3}, {%4,%5,%6,%7}, {%8,%9}, {%0,%1,%2,%3};\n"
                        : "+f"(acc[mt][nt][0]), "+f"(acc[mt][nt][1]),
                          "+f"(acc[mt][nt][2]), "+f"(acc[mt][nt][3])
                        : "r"(a[mt][0]), "r"(a[mt][1]), "r"(a[mt][2]), "r"(a[mt][3]),
                          "r"(b[nt][0]), "r"(b[nt][1]));
        }
        __syncthreads();
        if (kt + 2 < nk) load_tile(kt + 2);
    }

    // epilogue
    const int row0 = bm + wm * 64 + gm;
    const int col0 = bn + wn * 32 + tg * 2;
    #pragma unroll
    for (int mt = 0; mt < 4; mt++) {
        #pragma unroll
        for (int nt = 0; nt < 4; nt++) {
            const int r = row0 + mt * 16;
            const int c = col0 + nt * 8;
            float v0 = acc[mt][nt][0], v1 = acc[mt][nt][1];
            float v2 = acc[mt][nt][2], v3 = acc[mt][nt][3];
            if (ROUND_OUT) { v0 = rna_f(v0); v1 = rna_f(v1); v2 = rna_f(v2); v3 = rna_f(v3); }
            *reinterpret_cast<float2*>(D + (size_t)r * Nout + c)       = make_float2(v0, v1);
            *reinterpret_cast<float2*>(D + (size_t)(r + 8) * Nout + c) = make_float2(v2, v3);
        }
    }
#endif
}

// ---------------- host launch ----------------
extern "C" void kernel_launch(void* const* d_in, const int* in_sizes, int n_in,
                              void* d_out, int out_size)
{
    const float* x  = (const float*)d_in[0];   // [8192, 4096]
    const float* U  = (const float*)d_in[1];   // [4096, 1024]
    const float* S  = (const float*)d_in[2];   // [1024]
    const float* Vh = (const float*)d_in[3];   // [1024, 4096]
    float* y = (float*)d_out;                  // [8192, 4096]

    float *X, *W1, *W2, *T;
    cudaGetSymbolAddress((void**)&X,  g_X);
    cudaGetSymbolAddress((void**)&W1, g_W1);
    cudaGetSymbolAddress((void**)&W2, g_W2);
    cudaGetSymbolAddress((void**)&T,  g_T);

    cudaFuncSetAttribute(gemm_nt<true>,
                         cudaFuncAttributeMaxDynamicSharedMemorySize, SMEM_TOTAL);
    cudaFuncSetAttribute(gemm_nt<false>,
                         cudaFuncAttributeMaxDynamicSharedMemorySize, SMEM_TOTAL);

    // prepass: rna-round x, U; fold S into Vh rows (rna-rounded)
    prep_round<<<2048, 256>>>(x, X, (M_TOT * DIN) / 4);
    prep_round<<<1024, 256>>>(U, W2, (DOUT * RANK) / 4);
    prep_scale_round<<<dim3(DIN / 4 / 256, RANK), 256>>>(Vh, S, W1, DIN / 4);

    // GEMM 1: T[8192,1024] = X @ W1^T  (T stored tf32-rounded)
    gemm_nt<true><<<dim3(RANK / BN, M_TOT / BM), THREADS, SMEM_TOTAL>>>(X, W1, T, DIN, RANK);
    // GEMM 2: y[8192,4096] = T @ W2^T
    gemm_nt<false><<<dim3(DOUT / BN, M_TOT / BM), THREADS, SMEM_TOTAL>>>(T, W2, y, RANK, DOUT);
}

// round 4
// speedup vs baseline: 3.5210x; 1.1421x over previous
#include <cuda_runtime.h>
#include <cstdint>
#include <cstddef>

// ---------------- problem constants ----------------
#define M_TOT 8192
#define DIN   4096
#define DOUT  4096
#define RANK  1024

// ---------------- tiling (pair tile 256 x 512, BK=32) ----------------
#define TM 256                 // M per CTA pair (128 per CTA)
#define TN 512                 // N per pair (two N=256 dispatches)
#define BK 32
#define NSTAGE 4
#define THREADS 512

#define A_STAGE_BYTES (128 * BK * 4)   // 16384 (this CTA's 128 M-rows)
#define B_STAGE_BYTES (256 * BK * 4)   // 32768 (this CTA's 256 B-rows: 128 per dispatch)
#define SMEM_A_OFF 1024
#define SMEM_B_OFF (SMEM_A_OFF + NSTAGE * A_STAGE_BYTES)   // 66560
#define SMEM_TOTAL (SMEM_B_OFF + NSTAGE * B_STAGE_BYTES)   // 197632

// control block (first 1KB of smem)
#define OFF_TMEM  0
#define OFF_FULL  16     // 4 x 8B
#define OFF_EMPTY 48     // 4 x 8B
#define OFF_DONE  80

// idesc: kind::tf32, D=f32(1), A=tf32(2), B=tf32(2), N=256 -> 32<<17, M=256 -> 16<<24
#define IDESC_CG2 ((1u << 4) | (2u << 7) | (2u << 10) | ((256u / 8u) << 17) | ((256u / 16u) << 24))

// SW128 K-major smem descriptor base (layout=2, version=1, SBO=64, LBO=1)
#define DESC_BASE_SW128 \
    ((uint64_t(2) << 61) | (uint64_t(1) << 46) | (uint64_t(64) << 32) | (uint64_t(1) << 16))

#if defined(__CUDA_ARCH__) && (defined(__CUDA_ARCH_FEAT_SM103_ALL) || defined(__CUDA_ARCH_FEAT_SM100_ALL) || defined(__CUDA_ARCH_FEAT_SM101_ALL))
#define TC_PATH 1
#else
#define TC_PATH 0
#endif

// ---------------- scratch (allocation-free) ----------------
__device__ __align__(16) float g_W1[(size_t)RANK  * DIN];   // rna(S[r] * Vh[r,k])
__device__ __align__(16) float g_W2[(size_t)DOUT  * RANK];  // rna(U)
__device__ __align__(16) float g_T [(size_t)M_TOT * RANK];  // intermediate (tf32-rounded)

// ---------------- helpers ----------------
__device__ __forceinline__ uint32_t f2tf32(float f) {
    uint32_t u;
    asm("cvt.rna.tf32.f32 %0, %1;" : "=r"(u) : "f"(f));
    return u;
}
__device__ __forceinline__ float rna_f(float f) { return __uint_as_float(f2tf32(f)); }

__device__ __forceinline__ uint32_t smem_u32(const void* p) {
    uint32_t a;
    asm("{ .reg .u64 t; cvta.to.shared.u64 t, %1; cvt.u32.u64 %0, t; }" : "=r"(a) : "l"(p));
    return a;
}
__device__ __forceinline__ void cp_async16(uint32_t saddr, const void* g) {
    asm volatile("cp.async.cg.shared.global [%0], [%1], 16;\n" :: "r"(saddr), "l"(g));
}
__device__ __forceinline__ uint32_t sw128(uint32_t o) { return o ^ ((o >> 3) & 0x70); }

#if TC_PATH
__device__ __forceinline__ void mbar_init(uint32_t a, uint32_t cnt) {
    asm volatile("mbarrier.init.shared.b64 [%0], %1;" :: "r"(a), "r"(cnt) : "memory");
}
// arrive on cluster-rank-0's mbarrier at the same smem offset
__device__ __forceinline__ void mbar_arrive_rank0(uint32_t a) {
    asm volatile(
        "{\n\t"
        ".reg .b32 r;\n\t"
        "mapa.shared::cluster.u32 r, %0, 0;\n\t"
        "mbarrier.arrive.shared::cluster.b64 _, [r];\n\t"
        "}" :: "r"(a) : "memory");
}
__device__ __forceinline__ void mbar_wait(uint32_t a, uint32_t parity) {
    asm volatile(
        "{\n\t"
        ".reg .pred P;\n\t"
        "W_%=:\n\t"
        "mbarrier.try_wait.parity.acquire.cluster.shared::cta.b64 P, [%0], %1, 0x989680;\n\t"
        "@!P bra.uni W_%=;\n\t"
        "}" :: "r"(a), "r"(parity) : "memory");
}
__device__ __forceinline__ void mma_tf32_cg2(uint32_t d_tmem, uint64_t a_desc, uint64_t b_desc,
                                             uint32_t enable_d) {
    asm volatile(
        "{\n\t"
        ".reg .pred p;\n\t"
        "setp.ne.u32 p, %4, 0;\n\t"
        "tcgen05.mma.cta_group::2.kind::tf32 [%0], %1, %2, %3, "
        "{%5,%5,%5,%5,%5,%5,%5,%5}, p;\n\t"
        "}"
        :: "r"(d_tmem), "l"(a_desc), "l"(b_desc), "r"(IDESC_CG2), "r"(enable_d), "r"(0u)
        : "memory");
}
__device__ __forceinline__ void tc_commit_mc(uint32_t mbar) {
    asm volatile(
        "tcgen05.commit.cta_group::2.mbarrier::arrive::one.shared::cluster.multicast::cluster.b64 [%0], %1;"
        :: "r"(mbar), "h"((uint16_t)0x3) : "memory");
}
__device__ __forceinline__ void ldtm_x32(uint32_t* r, uint32_t addr) {
    asm volatile(
        "tcgen05.ld.sync.aligned.32x32b.x32.b32 "
        "{%0, %1, %2, %3, %4, %5, %6, %7, "
        " %8, %9, %10, %11, %12, %13, %14, %15, "
        " %16, %17, %18, %19, %20, %21, %22, %23, "
        " %24, %25, %26, %27, %28, %29, %30, %31}, [%32];"
        : "=r"(r[0]),  "=r"(r[1]),  "=r"(r[2]),  "=r"(r[3]),
          "=r"(r[4]),  "=r"(r[5]),  "=r"(r[6]),  "=r"(r[7]),
          "=r"(r[8]),  "=r"(r[9]),  "=r"(r[10]), "=r"(r[11]),
          "=r"(r[12]), "=r"(r[13]), "=r"(r[14]), "=r"(r[15]),
          "=r"(r[16]), "=r"(r[17]), "=r"(r[18]), "=r"(r[19]),
          "=r"(r[20]), "=r"(r[21]), "=r"(r[22]), "=r"(r[23]),
          "=r"(r[24]), "=r"(r[25]), "=r"(r[26]), "=r"(r[27]),
          "=r"(r[28]), "=r"(r[29]), "=r"(r[30]), "=r"(r[31])
        : "r"(addr));
}
#define CLUSTER_SYNC() do { \
    asm volatile("barrier.cluster.arrive.aligned;" ::: "memory"); \
    asm volatile("barrier.cluster.wait.aligned;" ::: "memory"); \
} while (0)
#endif  // TC_PATH

// ---------------- prepass kernels ----------------
__global__ void prep_round(const float* __restrict__ in, float* __restrict__ out, int n4) {
    int i = blockIdx.x * blockDim.x + threadIdx.x;
    int stride = gridDim.x * blockDim.x;
    for (; i < n4; i += stride) {
        float4 v = reinterpret_cast<const float4*>(in)[i];
        v.x = rna_f(v.x); v.y = rna_f(v.y); v.z = rna_f(v.z); v.w = rna_f(v.w);
        reinterpret_cast<float4*>(out)[i] = v;
    }
}
__global__ void prep_scale_round(const float* __restrict__ Vh, const float* __restrict__ S,
                                 float* __restrict__ out, int cols4) {
    int r = blockIdx.y;
    float s = __ldg(S + r);
    int c = blockIdx.x * blockDim.x + threadIdx.x;
    if (c < cols4) {
        float4 v = reinterpret_cast<const float4*>(Vh + (size_t)r * (cols4 * 4))[c];
        v.x = rna_f(v.x * s); v.y = rna_f(v.y * s); v.z = rna_f(v.z * s); v.w = rna_f(v.w * s);
        reinterpret_cast<float4*>(out + (size_t)r * (cols4 * 4))[c] = v;
    }
}

// ---------------- cg2 GEMM: D[M,Nout] = A[M,K] @ B[Nout,K]^T ----------------
// ROUND_A: A is raw fp32; producers LDG + rna-round + STS (GEMM1's x path).
// ROUND_OUT: round result to tf32 before store (T for GEMM2).
template <bool ROUND_A, bool ROUND_OUT>
__global__ __launch_bounds__(THREADS, 1) __cluster_dims__(2, 1, 1)
void gemm_cg2(const float* __restrict__ A, const float* __restrict__ Bm,
              float* __restrict__ D, int K, int Nout)
{
    extern __shared__ char smem[];
    const uint32_t sbase = smem_u32(smem);
    const int tid  = threadIdx.x;
    const int warp = tid >> 5;
    const int lane = tid & 31;
    const int rank = blockIdx.x & 1;                 // cluster rank
    const int bn   = (blockIdx.x >> 1) * TN;
    const int bm   = blockIdx.y * TM;
    const int nk   = K / BK;

#if TC_PATH
    if (warp == 0) {
        asm volatile("tcgen05.alloc.cta_group::2.sync.aligned.shared::cta.b32 [%0], %1;"
                     :: "r"(sbase + OFF_TMEM), "r"(512u) : "memory");
        asm volatile("tcgen05.relinquish_alloc_permit.cta_group::2.sync.aligned;");
    }
    if (tid == 0) {
        #pragma unroll
        for (int s = 0; s < NSTAGE; s++) {
            mbar_init(sbase + OFF_FULL  + 8 * s, 512);  // producers of BOTH CTAs
            mbar_init(sbase + OFF_EMPTY + 8 * s, 1);    // one multicast commit
        }
        mbar_init(sbase + OFF_DONE, 1);
    }
    __syncthreads();
    CLUSTER_SYNC();   // barriers + TMEM alloc visible cluster-wide before traffic

    uint32_t tmem_base;
    asm volatile("ld.shared.b32 %0, [%1];" : "=r"(tmem_base) : "r"(sbase + OFF_TMEM));

    if (warp >= 8) {
        // -------- producers: 256 threads per CTA --------
        const int pt = tid - 256;
        int e_stage = 0, e_phase = 1;
        int pending = -1;
        const float* Agb = A + (size_t)(bm + rank * 128) * K;   // this CTA's 128 M-rows
        for (int kt = 0; kt < nk; kt++) {
            const int s = e_stage;
            mbar_wait(sbase + OFF_EMPTY + 8 * s, (uint32_t)e_phase);
            if (++e_stage == NSTAGE) { e_stage = 0; e_phase ^= 1; }

            const float* Ag = Agb + (size_t)kt * BK;
            const uint32_t sA = sbase + SMEM_A_OFF + s * A_STAGE_BYTES;

            float4 av[4];
            if (ROUND_A) {
                #pragma unroll
                for (int i = 0; i < 4; i++) {        // A: 1024 granules / 256 thr
                    int idx = pt + 256 * i;
                    int r = idx >> 3, g = idx & 7;
                    av[i] = __ldg(reinterpret_cast<const float4*>(Ag + (size_t)r * K + g * 4));
                }
            } else {
                #pragma unroll
                for (int i = 0; i < 4; i++) {
                    int idx = pt + 256 * i;
                    int r = idx >> 3, g = idx & 7;
                    cp_async16(sA + sw128((uint32_t)(r * 128 + g * 16)),
                               Ag + (size_t)r * K + g * 4);
                }
            }
            // B: this CTA's 256 rows: dispatch d cols = bn + d*256 + rank*128 + j
            const uint32_t sB = sbase + SMEM_B_OFF + s * B_STAGE_BYTES;
            #pragma unroll
            for (int i = 0; i < 8; i++) {            // 2048 granules / 256 thr
                int idx = pt + 256 * i;
                int rl = idx >> 3, g = idx & 7;      // local row 0..255
                int d = rl >> 7, j = rl & 127;
                const float* src = Bm + (size_t)(bn + d * 256 + rank * 128 + j) * K
                                      + (size_t)kt * BK + g * 4;
                cp_async16(sB + sw128((uint32_t)(rl * 128 + g * 16)), src);
            }
            asm volatile("cp.async.commit_group;\n");

            if (ROUND_A) {
                #pragma unroll
                for (int i = 0; i < 4; i++) {
                    int idx = pt + 256 * i;
                    int r = idx >> 3, g = idx & 7;
                    float4 v = av[i];
                    v.x = rna_f(v.x); v.y = rna_f(v.y); v.z = rna_f(v.z); v.w = rna_f(v.w);
                    *reinterpret_cast<float4*>(smem + SMEM_A_OFF + s * A_STAGE_BYTES +
                                               sw128((uint32_t)(r * 128 + g * 16))) = v;
                }
            }

            if (pending >= 0) {
                asm volatile("cp.async.wait_group 1;\n");
                asm volatile("fence.proxy.async.shared::cta;\n");
                mbar_arrive_rank0(sbase + OFF_FULL + 8 * pending);
            }
            pending = s;
        }
        asm volatile("cp.async.wait_group 0;\n");
        asm volatile("fence.proxy.async.shared::cta;\n");
        mbar_arrive_rank0(sbase + OFF_FULL + 8 * pending);
    } else if (rank == 0 && warp == 0 && lane == 0) {
        // -------- MMA issuer: one thread in leader CTA --------
        int f_stage = 0, f_phase = 0;
        for (int kt = 0; kt < nk; kt++) {
            const int s = f_stage;
            mbar_wait(sbase + OFF_FULL + 8 * s, (uint32_t)f_phase);
            if (++f_stage == NSTAGE) { f_stage = 0; f_phase ^= 1; }

            uint64_t adesc = DESC_BASE_SW128 |
                (((uint64_t)((sbase + SMEM_A_OFF + s * A_STAGE_BYTES) >> 4)) & 0x3FFF);
            uint64_t bdesc = DESC_BASE_SW128 |
                (((uint64_t)((sbase + SMEM_B_OFF + s * B_STAGE_BYTES) >> 4)) & 0x3FFF);
            #pragma unroll
            for (int ks = 0; ks < 4; ks++) {         // 8 K-elements per dispatch
                uint32_t en = (uint32_t)(kt | ks);
                mma_tf32_cg2(tmem_base,       adesc + 2 * ks, bdesc + 2 * ks,        en);
                mma_tf32_cg2(tmem_base + 256, adesc + 2 * ks, bdesc + 1024 + 2 * ks, en);
            }
            tc_commit_mc(sbase + OFF_EMPTY + 8 * s);  // releases stage s in BOTH CTAs
        }
        tc_commit_mc(sbase + OFF_DONE);
    }

    // -------- epilogue --------
    mbar_wait(sbase + OFF_DONE, 0u);
    asm volatile("tcgen05.fence::after_thread_sync;" ::: "memory");

    if (warp < 8) {
        const size_t row = (size_t)(bm + rank * 128 + (warp & 3) * 32 + lane);
        const int colh = (warp >> 2) * 256;
        float* drow = D + row * Nout + bn + colh;
        #pragma unroll
        for (int c = 0; c < 8; c++) {
            uint32_t r[32];
            ldtm_x32(r, tmem_base + colh + 32 * c);
            asm volatile("tcgen05.wait::ld.sync.aligned;" ::: "memory");
            if (ROUND_OUT) {
                #pragma unroll
                for (int j = 0; j < 32; j++) r[j] = f2tf32(__uint_as_float(r[j]));
            }
            float4* dst = reinterpret_cast<float4*>(drow + 32 * c);
            #pragma unroll
            for (int q = 0; q < 8; q++)
                dst[q] = make_float4(__uint_as_float(r[4 * q + 0]), __uint_as_float(r[4 * q + 1]),
                                     __uint_as_float(r[4 * q + 2]), __uint_as_float(r[4 * q + 3]));
        }
        asm volatile("tcgen05.fence::before_thread_sync;" ::: "memory");
    }
    __syncthreads();
    if (warp == 0) {
        asm volatile("tcgen05.dealloc.cta_group::2.sync.aligned.b32 %0, %1;"
                     :: "r"(tmem_base), "r"(512u));
    }
    CLUSTER_SYNC();

#else
    // ================= non-accelerated fallback (never selected at runtime) =================
    // Plain fp32 smem-tiled GEMM for the CTA's 128x512 tile; full precision (no rounding needed).
    float* As = reinterpret_cast<float*>(smem + 1024);          // [128][33]
    float* Bs = As + 128 * 33;                                  // [128][33]
    const float* Ab = A + (size_t)(bm + rank * 128) * K;
    const int tr = tid >> 4;        // 0..31 -> 4 rows each
    const int tc = tid & 15;        // 0..15 -> 8 cols each
    for (int chunk = 0; chunk < 4; chunk++) {
        const float* Bb = Bm + (size_t)(bn + chunk * 128) * K;
        float acc[4][8];
        #pragma unroll
        for (int i = 0; i < 4; i++)
            #pragma unroll
            for (int j = 0; j < 8; j++) acc[i][j] = 0.f;
        for (int kt = 0; kt < nk; kt++) {
            #pragma unroll
            for (int j = 0; j < 2; j++) {
                int idx = tid + 512 * j;
                int r = idx >> 3, g = idx & 7;
                float4 va = *reinterpret_cast<const float4*>(Ab + (size_t)r * K + kt * BK + g * 4);
                float4 vb = *reinterpret_cast<const float4*>(Bb + (size_t)r * K + kt * BK + g * 4);
                *reinterpret_cast<float4*>(As + r * 33 + g * 4) = va;
                *reinterpret_cast<float4*>(Bs + r * 33 + g * 4) = vb;
            }
            __syncthreads();
            #pragma unroll 8
            for (int k = 0; k < BK; k++) {
                float a[4], b[8];
                #pragma unroll
                for (int i = 0; i < 4; i++) a[i] = As[(tr * 4 + i) * 33 + k];
                #pragma unroll
                for (int j = 0; j < 8; j++) b[j] = Bs[(tc * 8 + j) * 33 + k];
                #pragma unroll
                for (int i = 0; i < 4; i++)
                    #pragma unroll
                    for (int j = 0; j < 8; j++) acc[i][j] += a[i] * b[j];
            }
            __syncthreads();
        }
        #pragma unroll
        for (int i = 0; i < 4; i++)
            #pragma unroll
            for (int j = 0; j < 8; j++)
                D[(size_t)(bm + rank * 128 + tr * 4 + i) * Nout + bn + chunk * 128 + tc * 8 + j]
                    = acc[i][j];
    }
#endif
}

// ---------------- host launch ----------------
extern "C" void kernel_launch(void* const* d_in, const int* in_sizes, int n_in,
                              void* d_out, int out_size)
{
    const float* x  = (const float*)d_in[0];   // [8192, 4096]
    const float* U  = (const float*)d_in[1];   // [4096, 1024]
    const float* S  = (const float*)d_in[2];   // [1024]
    const float* Vh = (const float*)d_in[3];   // [1024, 4096]
    float* y = (float*)d_out;                  // [8192, 4096]

    float *W1, *W2, *T;
    cudaGetSymbolAddress((void**)&W1, g_W1);
    cudaGetSymbolAddress((void**)&W2, g_W2);
    cudaGetSymbolAddress((void**)&T,  g_T);

    cudaFuncSetAttribute((const void*)gemm_cg2<true, true>,
                         cudaFuncAttributeMaxDynamicSharedMemorySize, SMEM_TOTAL);
    cudaFuncSetAttribute((const void*)gemm_cg2<false, false>,
                         cudaFuncAttributeMaxDynamicSharedMemorySize, SMEM_TOTAL);

    // prepass: W1 = rna(S*Vh), W2 = rna(U)   (x rounding fused into GEMM1 producers)
    prep_scale_round<<<dim3(DIN / 4 / 256, RANK), 256>>>(Vh, S, W1, DIN / 4);
    prep_round<<<512, 256>>>(U, W2, (DOUT * RANK) / 4);

    // GEMM 1: T[8192,1024] = rna(x) @ W1^T   (T stored tf32-rounded)
    gemm_cg2<true, true><<<dim3(2 * (RANK / TN), M_TOT / TM), THREADS, SMEM_TOTAL>>>(
        x, W1, T, DIN, RANK);
    // GEMM 2: y[8192,4096] = T @ W2^T
    gemm_cg2<false, false><<<dim3(2 * (DOUT / TN), M_TOT / TM), THREADS, SMEM_TOTAL>>>(
        T, W2, y, RANK, DOUT);
}

// round 5
// speedup vs baseline: 3.6828x; 1.0459x over previous
#include <cuda_runtime.h>
#include <cstdint>
#include <cstddef>

// ---------------- problem constants ----------------
#define M_TOT 8192
#define DIN   4096
#define DOUT  4096
#define RANK  1024

// ---------------- tiling (pair tile 256 x 512, BK=32) ----------------
#define TM 256
#define TN 512
#define BK 32
#define NSTAGE 4
#define THREADS 512
#define NPAIRS 74
#define GRID_CTAS 148
#define MBLOCKS (M_TOT / TM)          // 32

#define A_STAGE_BYTES (128 * BK * 4)   // 16384
#define B_STAGE_BYTES (256 * BK * 4)   // 32768
#define SMEM_A_OFF 1024
#define SMEM_B_OFF (SMEM_A_OFF + NSTAGE * A_STAGE_BYTES)   // 66560
#define SMEM_TOTAL (SMEM_B_OFF + NSTAGE * B_STAGE_BYTES)   // 197632

// control block (first 1KB of smem)
#define OFF_TMEM  0
#define OFF_FULL  16     // 4 x 8B
#define OFF_EMPTY 48     // 4 x 8B
#define OFF_DONE  80
#define OFF_EPI   88

// idesc: kind::tf32, D=f32(1), A=tf32(2), B=tf32(2), N=256, M=256
#define IDESC_CG2 ((1u << 4) | (2u << 7) | (2u << 10) | ((256u / 8u) << 17) | ((256u / 16u) << 24))

// SW128 K-major smem descriptor base (layout=2, version=1, SBO=64, LBO=1)
#define DESC_BASE_SW128 \
    ((uint64_t(2) << 61) | (uint64_t(1) << 46) | (uint64_t(64) << 32) | (uint64_t(1) << 16))

#if defined(__CUDA_ARCH__) && (defined(__CUDA_ARCH_FEAT_SM103_ALL) || defined(__CUDA_ARCH_FEAT_SM100_ALL) || defined(__CUDA_ARCH_FEAT_SM101_ALL))
#define TC_PATH 1
#else
#define TC_PATH 0
#endif

// ---------------- scratch (allocation-free) ----------------
__device__ __align__(16) float g_W1[(size_t)RANK  * DIN];   // rna(S[r] * Vh[r,k])
__device__ __align__(16) float g_W2[(size_t)DOUT  * RANK];  // rna(U)
__device__ __align__(16) float g_T [(size_t)M_TOT * RANK];  // intermediate (tf32-rounded)

// ---------------- helpers ----------------
__device__ __forceinline__ uint32_t f2tf32(float f) {
    uint32_t u;
    asm("cvt.rna.tf32.f32 %0, %1;" : "=r"(u) : "f"(f));
    return u;
}
__device__ __forceinline__ float rna_f(float f) { return __uint_as_float(f2tf32(f)); }

__device__ __forceinline__ uint32_t smem_u32(const void* p) {
    uint32_t a;
    asm("{ .reg .u64 t; cvta.to.shared.u64 t, %1; cvt.u32.u64 %0, t; }" : "=r"(a) : "l"(p));
    return a;
}
__device__ __forceinline__ void cp_async16(uint32_t saddr, const void* g) {
    asm volatile("cp.async.cg.shared.global [%0], [%1], 16;\n" :: "r"(saddr), "l"(g));
}
__device__ __forceinline__ uint32_t sw128(uint32_t o) { return o ^ ((o >> 3) & 0x70); }

#if TC_PATH
__device__ __forceinline__ void mbar_init(uint32_t a, uint32_t cnt) {
    asm volatile("mbarrier.init.shared.b64 [%0], %1;" :: "r"(a), "r"(cnt) : "memory");
}
__device__ __forceinline__ void mbar_arrive_rank0(uint32_t a) {
    asm volatile(
        "{\n\t"
        ".reg .b32 r;\n\t"
        "mapa.shared::cluster.u32 r, %0, 0;\n\t"
        "mbarrier.arrive.shared::cluster.b64 _, [r];\n\t"
        "}" :: "r"(a) : "memory");
}
__device__ __forceinline__ void mbar_wait(uint32_t a, uint32_t parity) {
    asm volatile(
        "{\n\t"
        ".reg .pred P;\n\t"
        "W_%=:\n\t"
        "mbarrier.try_wait.parity.acquire.cluster.shared::cta.b64 P, [%0], %1, 0x989680;\n\t"
        "@!P bra.uni W_%=;\n\t"
        "}" :: "r"(a), "r"(parity) : "memory");
}
__device__ __forceinline__ void mma_tf32_cg2(uint32_t d_tmem, uint64_t a_desc, uint64_t b_desc,
                                             uint32_t enable_d) {
    asm volatile(
        "{\n\t"
        ".reg .pred p;\n\t"
        "setp.ne.u32 p, %4, 0;\n\t"
        "tcgen05.mma.cta_group::2.kind::tf32 [%0], %1, %2, %3, "
        "{%5,%5,%5,%5,%5,%5,%5,%5}, p;\n\t"
        "}"
        :: "r"(d_tmem), "l"(a_desc), "l"(b_desc), "r"(IDESC_CG2), "r"(enable_d), "r"(0u)
        : "memory");
}
__device__ __forceinline__ void tc_commit_mc(uint32_t mbar) {
    asm volatile(
        "tcgen05.commit.cta_group::2.mbarrier::arrive::one.shared::cluster.multicast::cluster.b64 [%0], %1;"
        :: "r"(mbar), "h"((uint16_t)0x3) : "memory");
}
__device__ __forceinline__ void ldtm_x32(uint32_t* r, uint32_t addr) {
    asm volatile(
        "tcgen05.ld.sync.aligned.32x32b.x32.b32 "
        "{%0, %1, %2, %3, %4, %5, %6, %7, "
        " %8, %9, %10, %11, %12, %13, %14, %15, "
        " %16, %17, %18, %19, %20, %21, %22, %23, "
        " %24, %25, %26, %27, %28, %29, %30, %31}, [%32];"
        : "=r"(r[0]),  "=r"(r[1]),  "=r"(r[2]),  "=r"(r[3]),
          "=r"(r[4]),  "=r"(r[5]),  "=r"(r[6]),  "=r"(r[7]),
          "=r"(r[8]),  "=r"(r[9]),  "=r"(r[10]), "=r"(r[11]),
          "=r"(r[12]), "=r"(r[13]), "=r"(r[14]), "=r"(r[15]),
          "=r"(r[16]), "=r"(r[17]), "=r"(r[18]), "=r"(r[19]),
          "=r"(r[20]), "=r"(r[21]), "=r"(r[22]), "=r"(r[23]),
          "=r"(r[24]), "=r"(r[25]), "=r"(r[26]), "=r"(r[27]),
          "=r"(r[28]), "=r"(r[29]), "=r"(r[30]), "=r"(r[31])
        : "r"(addr));
}
#define CLUSTER_SYNC() do { \
    asm volatile("barrier.cluster.arrive.aligned;" ::: "memory"); \
    asm volatile("barrier.cluster.wait.aligned;" ::: "memory"); \
} while (0)
#endif  // TC_PATH

// ---------------- prepass kernels ----------------
__global__ void prep_round(const float* __restrict__ in, float* __restrict__ out, int n4) {
    int i = blockIdx.x * blockDim.x + threadIdx.x;
    int stride = gridDim.x * blockDim.x;
    for (; i < n4; i += stride) {
        float4 v = reinterpret_cast<const float4*>(in)[i];
        v.x = rna_f(v.x); v.y = rna_f(v.y); v.z = rna_f(v.z); v.w = rna_f(v.w);
        reinterpret_cast<float4*>(out)[i] = v;
    }
}
__global__ void prep_scale_round(const float* __restrict__ Vh, const float* __restrict__ S,
                                 float* __restrict__ out, int cols4) {
    int r = blockIdx.y;
    float s = __ldg(S + r);
    int c = blockIdx.x * blockDim.x + threadIdx.x;
    if (c < cols4) {
        float4 v = reinterpret_cast<const float4*>(Vh + (size_t)r * (cols4 * 4))[c];
        v.x = rna_f(v.x * s); v.y = rna_f(v.y * s); v.z = rna_f(v.z * s); v.w = rna_f(v.w * s);
        reinterpret_cast<float4*>(out + (size_t)r * (cols4 * 4))[c] = v;
    }
}

// ---------------- persistent cg2 GEMM: D[M,Nout] = A[M,K] @ B[Nout,K]^T ----------------
// ROUND_A: producers LDG + rna + STS for A (GEMM1's x path). ROUND_OUT: tf32-round result.
template <bool ROUND_A, bool ROUND_OUT>
__global__ __launch_bounds__(THREADS, 1) __cluster_dims__(2, 1, 1)
void gemm_cg2(const float* __restrict__ A, const float* __restrict__ Bm,
              float* __restrict__ D, int K, int Nout, int ntiles)
{
    extern __shared__ char smem[];
    const uint32_t sbase = smem_u32(smem);
    const int tid  = threadIdx.x;
    const int warp = tid >> 5;
    const int lane = tid & 31;
    const int rank = blockIdx.x & 1;
    const int pair = blockIdx.x >> 1;
    const int nk   = K / BK;

#if TC_PATH
    if (warp == 0) {
        asm volatile("tcgen05.alloc.cta_group::2.sync.aligned.shared::cta.b32 [%0], %1;"
                     :: "r"(sbase + OFF_TMEM), "r"(512u) : "memory");
        asm volatile("tcgen05.relinquish_alloc_permit.cta_group::2.sync.aligned;");
    }
    if (tid == 0) {
        #pragma unroll
        for (int s = 0; s < NSTAGE; s++) {
            mbar_init(sbase + OFF_FULL  + 8 * s, 512);  // producers of both CTAs
            mbar_init(sbase + OFF_EMPTY + 8 * s, 1);    // one multicast commit
        }
        mbar_init(sbase + OFF_DONE, 1);
        mbar_init(sbase + OFF_EPI, 256);                // 4 warps x 32 x 2 CTAs
    }
    __syncthreads();
    CLUSTER_SYNC();

    uint32_t tmem_base;
    asm volatile("ld.shared.b32 %0, [%1];" : "=r"(tmem_base) : "r"(sbase + OFF_TMEM));

    if (warp >= 8) {
        // ================= producers: 256 threads, continuous stage ring =================
        const int pt = tid - 256;
        int e_stage = 0, e_phase = 1;
        int pending = -1;
        for (int t = pair; t < ntiles; t += NPAIRS) {
            const int bm = (t % MBLOCKS) * TM;
            const int bn = (t / MBLOCKS) * TN;
            const float* Agb = A + (size_t)(bm + rank * 128) * K;
            for (int kt = 0; kt < nk; kt++) {
                const int s = e_stage;
                mbar_wait(sbase + OFF_EMPTY + 8 * s, (uint32_t)e_phase);
                if (++e_stage == NSTAGE) { e_stage = 0; e_phase ^= 1; }

                const float* Ag = Agb + (size_t)kt * BK;
                const uint32_t sA = sbase + SMEM_A_OFF + s * A_STAGE_BYTES;

                float4 av[4];
                if (ROUND_A) {
                    #pragma unroll
                    for (int i = 0; i < 4; i++) {
                        int idx = pt + 256 * i;
                        int r = idx >> 3, g = idx & 7;
                        av[i] = __ldg(reinterpret_cast<const float4*>(Ag + (size_t)r * K + g * 4));
                    }
                } else {
                    #pragma unroll
                    for (int i = 0; i < 4; i++) {
                        int idx = pt + 256 * i;
                        int r = idx >> 3, g = idx & 7;
                        cp_async16(sA + sw128((uint32_t)(r * 128 + g * 16)),
                                   Ag + (size_t)r * K + g * 4);
                    }
                }
                const uint32_t sB = sbase + SMEM_B_OFF + s * B_STAGE_BYTES;
                #pragma unroll
                for (int i = 0; i < 8; i++) {
                    int idx = pt + 256 * i;
                    int rl = idx >> 3, g = idx & 7;
                    int d = rl >> 7, j = rl & 127;
                    const float* src = Bm + (size_t)(bn + d * 256 + rank * 128 + j) * K
                                          + (size_t)kt * BK + g * 4;
                    cp_async16(sB + sw128((uint32_t)(rl * 128 + g * 16)), src);
                }
                asm volatile("cp.async.commit_group;\n");

                if (ROUND_A) {
                    #pragma unroll
                    for (int i = 0; i < 4; i++) {
                        int idx = pt + 256 * i;
                        int r = idx >> 3, g = idx & 7;
                        float4 v = av[i];
                        v.x = rna_f(v.x); v.y = rna_f(v.y); v.z = rna_f(v.z); v.w = rna_f(v.w);
                        *reinterpret_cast<float4*>(smem + SMEM_A_OFF + s * A_STAGE_BYTES +
                                                   sw128((uint32_t)(r * 128 + g * 16))) = v;
                    }
                }
                if (pending >= 0) {
                    asm volatile("cp.async.wait_group 1;\n");
                    asm volatile("fence.proxy.async.shared::cta;\n");
                    mbar_arrive_rank0(sbase + OFF_FULL + 8 * pending);
                }
                pending = s;
            }
        }
        if (pending >= 0) {
            asm volatile("cp.async.wait_group 0;\n");
            asm volatile("fence.proxy.async.shared::cta;\n");
            mbar_arrive_rank0(sbase + OFF_FULL + 8 * pending);
        }
    } else if (rank == 0 && warp == 0 && lane == 0) {
        // ================= MMA issuer: one thread in leader CTA =================
        int f_stage = 0, f_phase = 0;
        int j = 0;
        for (int t = pair; t < ntiles; t += NPAIRS, j++) {
            if (j > 0) {   // wait for epilogue of previous tile to free TMEM
                mbar_wait(sbase + OFF_EPI, (uint32_t)((j - 1) & 1));
                asm volatile("tcgen05.fence::after_thread_sync;" ::: "memory");
            }
            for (int kt = 0; kt < nk; kt++) {
                const int s = f_stage;
                mbar_wait(sbase + OFF_FULL + 8 * s, (uint32_t)f_phase);
                if (++f_stage == NSTAGE) { f_stage = 0; f_phase ^= 1; }

                uint64_t adesc = DESC_BASE_SW128 |
                    (((uint64_t)((sbase + SMEM_A_OFF + s * A_STAGE_BYTES) >> 4)) & 0x3FFF);
                uint64_t bdesc = DESC_BASE_SW128 |
                    (((uint64_t)((sbase + SMEM_B_OFF + s * B_STAGE_BYTES) >> 4)) & 0x3FFF);
                #pragma unroll
                for (int ks = 0; ks < 4; ks++) {
                    uint32_t en = (uint32_t)(kt | ks);
                    mma_tf32_cg2(tmem_base,       adesc + 2 * ks, bdesc + 2 * ks,        en);
                    mma_tf32_cg2(tmem_base + 256, adesc + 2 * ks, bdesc + 1024 + 2 * ks, en);
                }
                tc_commit_mc(sbase + OFF_EMPTY + 8 * s);
            }
            tc_commit_mc(sbase + OFF_DONE);   // flips done parity for tile j
        }
    } else if (warp >= 4 && warp < 8) {
        // ================= epilogue: warps 4-7, one per TMEM subpartition =================
        int j = 0;
        for (int t = pair; t < ntiles; t += NPAIRS, j++) {
            mbar_wait(sbase + OFF_DONE, (uint32_t)(j & 1));
            asm volatile("tcgen05.fence::after_thread_sync;" ::: "memory");

            const int bm = (t % MBLOCKS) * TM;
            const int bn = (t / MBLOCKS) * TN;
            const size_t row = (size_t)(bm + rank * 128 + (warp & 3) * 32 + lane);
            float* drow = D + row * Nout + bn;
            #pragma unroll
            for (int c = 0; c < 16; c++) {
                uint32_t r[32];
                ldtm_x32(r, tmem_base + 32 * c);
                asm volatile("tcgen05.wait::ld.sync.aligned;" ::: "memory");
                if (ROUND_OUT) {
                    #pragma unroll
                    for (int q = 0; q < 32; q++) r[q] = f2tf32(__uint_as_float(r[q]));
                }
                float4* dst = reinterpret_cast<float4*>(drow + 32 * c);
                #pragma unroll
                for (int q = 0; q < 8; q++)
                    dst[q] = make_float4(__uint_as_float(r[4 * q + 0]), __uint_as_float(r[4 * q + 1]),
                                         __uint_as_float(r[4 * q + 2]), __uint_as_float(r[4 * q + 3]));
            }
            asm volatile("tcgen05.fence::before_thread_sync;" ::: "memory");
            mbar_arrive_rank0(sbase + OFF_EPI);    // free TMEM for next tile
        }
    }

    __syncthreads();
    if (warp == 0) {
        asm volatile("tcgen05.dealloc.cta_group::2.sync.aligned.b32 %0, %1;"
                     :: "r"(tmem_base), "r"(512u));
    }
    CLUSTER_SYNC();

#else
    // ================= non-accelerated fallback (compile-only) =================
    float* As = reinterpret_cast<float*>(smem + 1024);
    float* Bs = As + 128 * 33;
    const int tr = tid >> 4;
    const int tc = tid & 15;
    for (int t = pair; t < ntiles; t += NPAIRS) {
        const int bm = (t % MBLOCKS) * TM;
        const int bn = (t / MBLOCKS) * TN;
        const float* Ab = A + (size_t)(bm + rank * 128) * K;
        for (int chunk = 0; chunk < 4; chunk++) {
            const float* Bb = Bm + (size_t)(bn + chunk * 128) * K;
            float acc[4][8];
            #pragma unroll
            for (int i = 0; i < 4; i++)
                #pragma unroll
                for (int jj = 0; jj < 8; jj++) acc[i][jj] = 0.f;
            for (int kt = 0; kt < nk; kt++) {
                #pragma unroll
                for (int jj = 0; jj < 2; jj++) {
                    int idx = tid + 512 * jj;
                    int r = idx >> 3, g = idx & 7;
                    *reinterpret_cast<float4*>(As + r * 33 + g * 4) =
                        *reinterpret_cast<const float4*>(Ab + (size_t)r * K + kt * BK + g * 4);
                    *reinterpret_cast<float4*>(Bs + r * 33 + g * 4) =
                        *reinterpret_cast<const float4*>(Bb + (size_t)r * K + kt * BK + g * 4);
                }
                __syncthreads();
                #pragma unroll 8
                for (int k = 0; k < BK; k++) {
                    float a[4], b[8];
                    #pragma unroll
                    for (int i = 0; i < 4; i++) a[i] = As[(tr * 4 + i) * 33 + k];
                    #pragma unroll
                    for (int jj = 0; jj < 8; jj++) b[jj] = Bs[(tc * 8 + jj) * 33 + k];
                    #pragma unroll
                    for (int i = 0; i < 4; i++)
                        #pragma unroll
                        for (int jj = 0; jj < 8; jj++) acc[i][jj] += a[i] * b[jj];
                }
                __syncthreads();
            }
            #pragma unroll
            for (int i = 0; i < 4; i++)
                #pragma unroll
                for (int jj = 0; jj < 8; jj++)
                    D[(size_t)(bm + rank * 128 + tr * 4 + i) * Nout + bn + chunk * 128 + tc * 8 + jj]
                        = acc[i][jj];
        }
    }
#endif
}

// ---------------- host launch ----------------
extern "C" void kernel_launch(void* const* d_in, const int* in_sizes, int n_in,
                              void* d_out, int out_size)
{
    const float* x  = (const float*)d_in[0];   // [8192, 4096]
    const float* U  = (const float*)d_in[1];   // [4096, 1024]
    const float* S  = (const float*)d_in[2];   // [1024]
    const float* Vh = (const float*)d_in[3];   // [1024, 4096]
    float* y = (float*)d_out;                  // [8192, 4096]

    float *W1, *W2, *T;
    cudaGetSymbolAddress((void**)&W1, g_W1);
    cudaGetSymbolAddress((void**)&W2, g_W2);
    cudaGetSymbolAddress((void**)&T,  g_T);

    cudaFuncSetAttribute((const void*)gemm_cg2<true, true>,
                         cudaFuncAttributeMaxDynamicSharedMemorySize, SMEM_TOTAL);
    cudaFuncSetAttribute((const void*)gemm_cg2<false, false>,
                         cudaFuncAttributeMaxDynamicSharedMemorySize, SMEM_TOTAL);

    // prepass: W1 = rna(S*Vh), W2 = rna(U)
    prep_scale_round<<<dim3(DIN / 4 / 256, RANK), 256>>>(Vh, S, W1, DIN / 4);
    prep_round<<<512, 256>>>(U, W2, (DOUT * RANK) / 4);

    // GEMM 1: T = rna(x) @ W1^T   (64 tiles, 1 persistent wave)
    gemm_cg2<true, true><<<GRID_CTAS, THREADS, SMEM_TOTAL>>>(
        x, W1, T, DIN, RANK, MBLOCKS * (RANK / TN));
    // GEMM 2: y = T @ W2^T        (256 tiles, persistent)
    gemm_cg2<false, false><<<GRID_CTAS, THREADS, SMEM_TOTAL>>>(
        T, W2, y, RANK, DOUT, MBLOCKS * (DOUT / TN));
}